// round 3
// baseline (speedup 1.0000x reference)
#include <cuda_runtime.h>

#define HH 376
#define WW 376
#define HWX (HH*WW)          // 141376
#define NHM (3*HWX)          // 424128
#define KTOP 500
#define CANDS 4096

// ---------------- scratch (device globals: no allocation allowed) ----------------
__device__ float g_shared[64 * HWX];     // shared conv output (BN+ReLU)
__device__ float g_h[64 * HWX];          // hm branch conv1 output
__device__ float g_hm[3 * HWX];          // sigmoid heatmap
__device__ float g_Wsh_t[256 * 64 * 9];  // [ic][oc][9]
__device__ float g_W1t[6 * 64 * 64 * 9]; // [b][ic][oc][9]
__device__ float g_sc_sh[64], g_bi_sh[64];
__device__ float g_sc1[6 * 64], g_bi1[6 * 64];
__device__ unsigned int g_hist1[2048], g_hist2[2048];
__device__ unsigned int g_T1, g_above1, g_T2;
__device__ unsigned int g_cand_count;
__device__ float g_cand_val[CANDS];
__device__ int   g_cand_idx[CANDS];
__device__ float g_topk_val[512];
__device__ int   g_topk_idx[512];
__device__ float g_gather[5 * KTOP * 3]; // [branch-1][det][3]

// ---------------- small prep kernels ----------------
__global__ void zero_small_k() {
    int t = threadIdx.x;
    for (int i = t; i < 2048; i += 1024) { g_hist1[i] = 0u; g_hist2[i] = 0u; }
    if (t == 0) g_cand_count = 0u;
}

__global__ void zero_out_k(float* out, int n) {
    int i = blockIdx.x * blockDim.x + threadIdx.x;
    if (i < n) out[i] = 0.f;
}

__global__ void prep_bn_k(const float* __restrict__ bn_sh, const float* __restrict__ bn1s) {
    int c = threadIdx.x;
    if (c >= 64) return;
    float g = bn_sh[0*64+c], b = bn_sh[1*64+c], m = bn_sh[2*64+c], v = bn_sh[3*64+c];
    float sc = g * rsqrtf(v + 1e-5f);
    g_sc_sh[c] = sc; g_bi_sh[c] = b - m * sc;
    for (int br = 0; br < 6; br++) {
        const float* p = bn1s + br * 4 * 64;
        float g1 = p[0*64+c], b1 = p[1*64+c], m1 = p[2*64+c], v1 = p[3*64+c];
        float s1 = g1 * rsqrtf(v1 + 1e-5f);
        g_sc1[br*64+c] = s1; g_bi1[br*64+c] = b1 - m1 * s1;
    }
}

__global__ void transpose_wsh_k(const float* __restrict__ w) {
    int i = blockIdx.x * blockDim.x + threadIdx.x;
    if (i >= 64*256*9) return;
    int k = i % 9; int r = i / 9; int ic = r % 256; int oc = r / 256;
    g_Wsh_t[(ic*64 + oc)*9 + k] = w[i];
}

__global__ void transpose_w1_k(const float* __restrict__ w) {
    int i = blockIdx.x * blockDim.x + threadIdx.x;
    if (i >= 6*64*64*9) return;
    int k = i % 9; int r = i / 9; int ic = r % 64; r /= 64; int oc = r % 64; int b = r / 64;
    g_W1t[(((b*64 + ic)*64) + oc)*9 + k] = w[i];
}

// ---------------- 3x3 conv + BN + ReLU (Cout=64), register-tiled ----------------
// MODE 0: in = x (arg, 256 ch), weights g_Wsh_t, out g_shared
// MODE 1: in = g_shared (64 ch), weights g_W1t branch 0, out g_h
// block (32,8): thread (tx,ty) computes 8 y-pixels x 8 output channels (oc = ty*8..+8)
template<int MODE>
__global__ __launch_bounds__(256, 2)
void conv3x3_bnrelu_k(const float* __restrict__ xin)
{
    const int CIN = (MODE == 0) ? 256 : 64;
    const float* __restrict__ in = (MODE == 0) ? xin : g_shared;
    const float* __restrict__ wt = (MODE == 0) ? g_Wsh_t : g_W1t;
    const float* __restrict__ sc = (MODE == 0) ? g_sc_sh : g_sc1;
    const float* __restrict__ bi = (MODE == 0) ? g_bi_sh : g_bi1;
    float* __restrict__ out      = (MODE == 0) ? g_shared : g_h;

    __shared__ float s_in[10][34];
    __shared__ float s_w[576];
    const int tx = threadIdx.x, ty = threadIdx.y;
    const int tid = ty*32 + tx;
    const int x0 = blockIdx.x * 32;
    const int y0 = blockIdx.y * 8;

    float acc[8][8];
    #pragma unroll
    for (int a = 0; a < 8; a++)
        #pragma unroll
        for (int b = 0; b < 8; b++) acc[a][b] = 0.f;

    for (int ic = 0; ic < CIN; ic++) {
        for (int i = tid; i < 340; i += 256) {
            int r = i / 34, c = i % 34;
            int gy = y0 - 1 + r, gx = x0 - 1 + c;
            float v = 0.f;
            if (gy >= 0 && gy < HH && gx >= 0 && gx < WW)
                v = in[(size_t)ic*HWX + gy*WW + gx];
            s_in[r][c] = v;
        }
        for (int i = tid; i < 576; i += 256) s_w[i] = wt[ic*576 + i];
        __syncthreads();

        float rin[3][10];
        #pragma unroll
        for (int c = 0; c < 3; c++)
            #pragma unroll
            for (int r = 0; r < 10; r++) rin[c][r] = s_in[r][tx + c];

        #pragma unroll
        for (int ky = 0; ky < 3; ky++)
            #pragma unroll
            for (int kx = 0; kx < 3; kx++) {
                float wv[8];
                #pragma unroll
                for (int o = 0; o < 8; o++) wv[o] = s_w[(ty*8+o)*9 + ky*3 + kx];
                #pragma unroll
                for (int dy = 0; dy < 8; dy++) {
                    float v = rin[kx][dy + ky];
                    #pragma unroll
                    for (int o = 0; o < 8; o++) acc[dy][o] = fmaf(v, wv[o], acc[dy][o]);
                }
            }
        __syncthreads();
    }
    int x = x0 + tx;
    if (x >= WW) return;
    #pragma unroll
    for (int o = 0; o < 8; o++) {
        int oc = ty*8 + o;
        float s = sc[oc], b = bi[oc];
        #pragma unroll
        for (int dy = 0; dy < 8; dy++) {
            int y = y0 + dy;
            if (y < HH) {
                float v = fmaf(acc[dy][o], s, b);
                out[(size_t)oc*HWX + y*WW + x] = fmaxf(v, 0.f);
            }
        }
    }
}

// ---------------- hm final conv (64->3) + bias + sigmoid ----------------
__global__ __launch_bounds__(256)
void conv2_hm_k(const float* __restrict__ W2s, const float* __restrict__ b2s)
{
    const float* __restrict__ in = g_h;
    float* __restrict__ out = g_hm;
    __shared__ float s_in[10][34];
    __shared__ float s_w[27];
    const int tx = threadIdx.x, ty = threadIdx.y;
    const int tid = ty*32 + tx;
    const int x0 = blockIdx.x * 32;
    const int y0 = blockIdx.y * 8;
    float acc[3] = {0.f, 0.f, 0.f};

    for (int ic = 0; ic < 64; ic++) {
        for (int i = tid; i < 340; i += 256) {
            int r = i / 34, c = i % 34;
            int gy = y0 - 1 + r, gx = x0 - 1 + c;
            float v = 0.f;
            if (gy >= 0 && gy < HH && gx >= 0 && gx < WW)
                v = in[(size_t)ic*HWX + gy*WW + gx];
            s_in[r][c] = v;
        }
        if (tid < 27) {
            int o = tid / 9, k = tid % 9;
            s_w[tid] = W2s[(o*64 + ic)*9 + k]; // branch 0 base
        }
        __syncthreads();
        float r9[9];
        #pragma unroll
        for (int ky = 0; ky < 3; ky++)
            #pragma unroll
            for (int kx = 0; kx < 3; kx++) r9[ky*3+kx] = s_in[ty + ky][tx + kx];
        #pragma unroll
        for (int o = 0; o < 3; o++)
            #pragma unroll
            for (int k = 0; k < 9; k++) acc[o] = fmaf(r9[k], s_w[o*9+k], acc[o]);
        __syncthreads();
    }
    int x = x0 + tx, y = y0 + ty;
    if (x >= WW || y >= HH) return;
    #pragma unroll
    for (int o = 0; o < 3; o++) {
        float v = acc[o] + b2s[o];
        out[(size_t)o*HWX + y*WW + x] = 1.f / (1.f + expf(-v));
    }
}

// ---------------- top-k: 2-level radix-select on float bits + bitonic sort ----------------
__global__ void hist1_k() {
    __shared__ unsigned int h[2048];
    int t = threadIdx.x;
    for (int i = t; i < 2048; i += blockDim.x) h[i] = 0u;
    __syncthreads();
    for (int i = blockIdx.x * blockDim.x + t; i < NHM; i += gridDim.x * blockDim.x) {
        unsigned int bits = __float_as_uint(g_hm[i]);
        atomicAdd(&h[bits >> 21], 1u);
    }
    __syncthreads();
    for (int i = t; i < 2048; i += blockDim.x)
        if (h[i]) atomicAdd(&g_hist1[i], h[i]);
}

__global__ void select1_k() {
    __shared__ unsigned int s[2048];
    int t = threadIdx.x; // 1024
    s[t] = g_hist1[t]; s[t+1024] = g_hist1[t+1024];
    __syncthreads();
    for (int off = 1; off < 2048; off <<= 1) {
        unsigned int v0 = (t + off < 2048) ? s[t + off] : 0u;
        unsigned int v1 = (t + 1024 + off < 2048) ? s[t + 1024 + off] : 0u;
        __syncthreads();
        s[t] += v0; s[t+1024] += v1;
        __syncthreads();
    }
    for (int p = t; p < 2048; p += 1024) {
        if (s[p] >= KTOP && (p == 2047 || s[p+1] < KTOP)) {
            g_T1 = (unsigned int)p;
            g_above1 = (p < 2047) ? s[p+1] : 0u;
        }
    }
}

__global__ void hist2_k() {
    __shared__ unsigned int h[2048];
    int t = threadIdx.x;
    unsigned int T1 = g_T1;
    for (int i = t; i < 2048; i += blockDim.x) h[i] = 0u;
    __syncthreads();
    for (int i = blockIdx.x * blockDim.x + t; i < NHM; i += gridDim.x * blockDim.x) {
        unsigned int bits = __float_as_uint(g_hm[i]);
        if ((bits >> 21) == T1) atomicAdd(&h[(bits >> 10) & 0x7FFu], 1u);
    }
    __syncthreads();
    for (int i = t; i < 2048; i += blockDim.x)
        if (h[i]) atomicAdd(&g_hist2[i], h[i]);
}

__global__ void select2_k() {
    __shared__ unsigned int s[2048];
    int t = threadIdx.x;
    unsigned int need = KTOP - g_above1;
    s[t] = g_hist2[t]; s[t+1024] = g_hist2[t+1024];
    __syncthreads();
    for (int off = 1; off < 2048; off <<= 1) {
        unsigned int v0 = (t + off < 2048) ? s[t + off] : 0u;
        unsigned int v1 = (t + 1024 + off < 2048) ? s[t + 1024 + off] : 0u;
        __syncthreads();
        s[t] += v0; s[t+1024] += v1;
        __syncthreads();
    }
    for (int p = t; p < 2048; p += 1024) {
        if (s[p] >= need && (p == 2047 || s[p+1] < need)) g_T2 = (unsigned int)p;
    }
}

__global__ void compact_k() {
    unsigned int T1 = g_T1, T2 = g_T2;
    for (int i = blockIdx.x * blockDim.x + threadIdx.x; i < NHM; i += gridDim.x * blockDim.x) {
        float v = g_hm[i];
        unsigned int bits = __float_as_uint(v);
        unsigned int b1 = bits >> 21;
        bool take = (b1 > T1) || (b1 == T1 && ((bits >> 10) & 0x7FFu) >= T2);
        if (take) {
            unsigned int pos = atomicAdd(&g_cand_count, 1u);
            if (pos < CANDS) { g_cand_val[pos] = v; g_cand_idx[pos] = i; }
        }
    }
}

__global__ void sort_topk_k() {
    __shared__ float sv[CANDS];
    __shared__ int   si[CANDS];
    int t = threadIdx.x; // 1024
    unsigned int M = g_cand_count; if (M > CANDS) M = CANDS;
    for (int e = t; e < CANDS; e += 1024) {
        if (e < (int)M) { sv[e] = g_cand_val[e]; si[e] = g_cand_idx[e]; }
        else            { sv[e] = -1.f;          si[e] = 0x7fffffff; }
    }
    __syncthreads();
    for (int k = 2; k <= CANDS; k <<= 1) {
        for (int j = k >> 1; j > 0; j >>= 1) {
            for (int e = t; e < CANDS; e += 1024) {
                int p = e ^ j;
                if (p > e) {
                    bool asc = ((e & k) == 0);
                    float va = sv[e], vb = sv[p];
                    int   ia = si[e], ib = si[p];
                    bool b_first = (vb > va) || (vb == va && ib < ia);
                    if (b_first == asc) { sv[e]=vb; sv[p]=va; si[e]=ib; si[p]=ia; }
                }
            }
            __syncthreads();
        }
    }
    if (t < KTOP) { g_topk_val[t] = sv[t]; g_topk_idx[t] = si[t]; }
}

// ---------------- sparse branch eval (branches 1..5 at 500 positions) ----------------
__device__ __forceinline__ float acc_out(const float* sm_in, const float* sm_w, int o, int ic0) {
    int p = o / 64, oc = o % 64, py = p / 3, px = p % 3;
    float part = 0.f;
    #pragma unroll
    for (int icl = 0; icl < 8; icl++) {
        const float* wrow = sm_w + icl*576 + oc*9;
        #pragma unroll
        for (int ky = 0; ky < 3; ky++)
            #pragma unroll
            for (int kx = 0; kx < 3; kx++) {
                int pin = (py + ky)*5 + (px + kx);
                part = fmaf(sm_in[pin*64 + ic0 + icl], wrow[ky*3+kx], part);
            }
    }
    return part;
}

__global__ __launch_bounds__(256)
void sparse_branch_k(const float* __restrict__ W2s, const float* __restrict__ b2s) {
    __shared__ float sm_in[25*64];
    __shared__ float sm_w[8*576];
    __shared__ float sm_h[576];
    int det = blockIdx.x;
    int b = blockIdx.y + 1; // branches 1..5
    int tid = threadIdx.x;
    int idx = g_topk_idx[det];
    int sp = idx % HWX;
    int cy = sp / WW, cx = sp % WW;

    for (int i = tid; i < 1600; i += 256) {
        int p = i / 64, ic = i % 64;
        int gy = cy + p/5 - 2, gx = cx + p%5 - 2;
        float v = 0.f;
        if (gy >= 0 && gy < HH && gx >= 0 && gx < WW)
            v = g_shared[(size_t)ic*HWX + gy*WW + gx];
        sm_in[p*64 + ic] = v;
    }
    __syncthreads();

    float a0 = 0.f, a1 = 0.f, a2 = 0.f;
    for (int c = 0; c < 8; c++) {
        int ic0 = c * 8;
        const float* wb = g_W1t + (size_t)(b*64 + ic0) * 576;
        for (int i = tid; i < 4608; i += 256) sm_w[i] = wb[i];
        __syncthreads();
        a0 += acc_out(sm_in, sm_w, tid,       ic0);
        a1 += acc_out(sm_in, sm_w, tid + 256, ic0);
        if (tid < 64) a2 += acc_out(sm_in, sm_w, tid + 512, ic0);
        __syncthreads();
    }

    // BN + ReLU + zero out-of-image conv1 pixels
    {
        float accs[3] = {a0, a1, a2};
        int os[3] = {tid, tid + 256, tid + 512};
        #pragma unroll
        for (int q = 0; q < 3; q++) {
            int o = os[q];
            if (o < 576) {
                int p = o / 64, oc = o % 64;
                float v = fmaf(accs[q], g_sc1[b*64+oc], g_bi1[b*64+oc]);
                v = fmaxf(v, 0.f);
                int gy = cy + p/3 - 1, gx = cx + p%3 - 1;
                if (gy < 0 || gy >= HH || gx < 0 || gx >= WW) v = 0.f;
                sm_h[p*64 + oc] = v;
            }
        }
    }
    __syncthreads();

    int warp = tid >> 5, lane = tid & 31;
    if (warp < 3) {
        const float* w2 = W2s + (size_t)((b*3 + warp) * 64) * 9;
        float sum = 0.f;
        for (int t2 = lane; t2 < 576; t2 += 32) {
            int oc = t2 / 9, p = t2 % 9;
            sum = fmaf(sm_h[p*64 + oc], w2[t2], sum);
        }
        #pragma unroll
        for (int off = 16; off > 0; off >>= 1)
            sum += __shfl_down_sync(0xFFFFFFFFu, sum, off);
        if (lane == 0)
            g_gather[((b-1)*KTOP + det)*3 + warp] = sum + b2s[b*3 + warp];
    }
}

// ---------------- decode ----------------
__global__ void decode_k(float* __restrict__ out) {
    int k = blockIdx.x * blockDim.x + threadIdx.x;
    if (k >= KTOP) return;
    float s = g_topk_val[k];
    int idx = g_topk_idx[k];
    int cls = idx / HWX;
    int sp  = idx % HWX;
    float ys = (float)(sp / WW);
    float xs = (float)(sp % WW);
    const float* gC = &g_gather[(0*KTOP + k)*3];
    const float* gZ = &g_gather[(1*KTOP + k)*3];
    const float* gD = &g_gather[(2*KTOP + k)*3];
    const float* gR = &g_gather[(3*KTOP + k)*3];
    const float* gI = &g_gather[(4*KTOP + k)*3];
    float xg = (xs + gC[0]) * 0.4f - 75.2f;
    float yg = (ys + gC[1]) * 0.4f - 75.2f;
    float cz = gZ[0];
    float d0 = expf(gD[0]), d1 = expf(gD[1]), d2 = expf(gD[2]);
    float heading = atan2f(gR[1], gR[0]);
    float iou = (gI[0] + 1.f) * 0.5f;
    iou = fminf(fmaxf(iou, 0.f), 1.f);
    const float rect[3] = {0.68f, 0.71f, 0.65f};
    float r = rect[cls];
    float sc = powf(s, 1.f - r) * powf(iou, r);
    if (!(sc > 0.1f)) sc = 0.f;
    out[k*7 + 0] = xg;
    out[k*7 + 1] = yg;
    out[k*7 + 2] = cz;
    out[k*7 + 3] = d0;
    out[k*7 + 4] = d1;
    out[k*7 + 5] = d2;
    out[k*7 + 6] = heading;
    out[KTOP*7 + k] = sc;            // scores at 3500..3999
    out[KTOP*7 + KTOP + k] = (float)cls; // cls at 4000..4499
}

// ---------------- launch ----------------
extern "C" void kernel_launch(void* const* d_in, const int* in_sizes, int n_in,
                              void* d_out, int out_size) {
    const float* x     = (const float*)d_in[0];
    const float* W_sh  = (const float*)d_in[1];
    const float* bn_sh = (const float*)d_in[2];
    const float* W1s   = (const float*)d_in[3];
    const float* bn1s  = (const float*)d_in[4];
    const float* W2s   = (const float*)d_in[5];
    const float* b2s   = (const float*)d_in[6];
    float* out = (float*)d_out;

    zero_small_k<<<1, 1024>>>();
    zero_out_k<<<(out_size + 255)/256, 256>>>(out, out_size);
    prep_bn_k<<<1, 64>>>(bn_sh, bn1s);
    transpose_wsh_k<<<(64*256*9 + 511)/512, 512>>>(W_sh);
    transpose_w1_k<<<(6*64*64*9 + 511)/512, 512>>>(W1s);

    dim3 cgrid(12, 47), cblk(32, 8);
    conv3x3_bnrelu_k<0><<<cgrid, cblk>>>(x);        // shared conv 256->64
    conv3x3_bnrelu_k<1><<<cgrid, cblk>>>(nullptr);  // hm conv1 64->64
    conv2_hm_k<<<cgrid, cblk>>>(W2s, b2s);

    hist1_k<<<512, 512>>>();
    select1_k<<<1, 1024>>>();
    hist2_k<<<512, 512>>>();
    select2_k<<<1, 1024>>>();
    compact_k<<<512, 512>>>();
    sort_topk_k<<<1, 1024>>>();

    dim3 sgrid(KTOP, 5);
    sparse_branch_k<<<sgrid, 256>>>(W2s, b2s);
    decode_k<<<2, 256>>>(out);
}